// round 16
// baseline (speedup 1.0000x reference)
#include <cuda_runtime.h>
#include <cuda_bf16.h>
#include <math.h>
#include <stdint.h>

#define BT   4096      // B*T
#define CD   768       // C
#define TT   1024      // T
#define NH   12
#define HDIM 64
#define NE   16
#define DFF  3072
#define QKVW 2304      // 3*C

// ---------------- scratch (device globals: allocation-free kernel_launch) ----
__device__ float g_xn  [BT * CD];
__device__ float g_qkv [BT * QKVW];
__device__ float g_y   [BT * CD];
__device__ float g_x1  [BT * CD];
__device__ float g_xn2 [BT * CD];
__device__ float g_part[2 * BT * CD];
__device__ float g_H   [NE * BT * DFF];
__device__ int   g_cnt [NE];
__device__ int   g_tok [NE * BT];
__device__ int   g_slot[NE * BT];
__device__ float g_gate[NE * BT];

// ---------------- LayerNorm ---------------------------------------------------
__global__ __launch_bounds__(256) void ln_kernel(
    const float* __restrict__ x, const float* __restrict__ w,
    const float* __restrict__ b, float* __restrict__ out)
{
    const int row = blockIdx.x;
    const int t = threadIdx.x;
    const float* xr = x + (size_t)row * CD;
    __shared__ float sh[8];

    float a0 = xr[t], a1 = xr[t + 256], a2 = xr[t + 512];
    float s = a0 + a1 + a2;
    #pragma unroll
    for (int m = 16; m >= 1; m >>= 1) s += __shfl_xor_sync(0xffffffffu, s, m);
    if ((t & 31) == 0) sh[t >> 5] = s;
    __syncthreads();
    float mu = 0.f;
    #pragma unroll
    for (int i = 0; i < 8; i++) mu += sh[i];
    mu *= (1.0f / CD);
    __syncthreads();

    float d0 = a0 - mu, d1 = a1 - mu, d2 = a2 - mu;
    float v = d0 * d0 + d1 * d1 + d2 * d2;
    #pragma unroll
    for (int m = 16; m >= 1; m >>= 1) v += __shfl_xor_sync(0xffffffffu, v, m);
    if ((t & 31) == 0) sh[t >> 5] = v;
    __syncthreads();
    float var = 0.f;
    #pragma unroll
    for (int i = 0; i < 8; i++) var += sh[i];
    var *= (1.0f / CD);
    const float rstd = rsqrtf(var + 1e-5f);

    float* orow = out + (size_t)row * CD;
    orow[t      ] = d0 * rstd * w[t      ] + b[t      ];
    orow[t + 256] = d1 * rstd * w[t + 256] + b[t + 256];
    orow[t + 512] = d2 * rstd * w[t + 512] + b[t + 512];
}

// ---------------- bf16 helpers ------------------------------------------------
__device__ __forceinline__ void split_pack(float x0, float x1,
                                           unsigned& hi, unsigned& lo)
{
    __nv_bfloat16 h0 = __float2bfloat16(x0);
    __nv_bfloat16 h1 = __float2bfloat16(x1);
    float r0 = x0 - __bfloat162float(h0);
    float r1 = x1 - __bfloat162float(h1);
    __nv_bfloat16 l0 = __float2bfloat16(r0);
    __nv_bfloat16 l1 = __float2bfloat16(r1);
    __nv_bfloat162 hp = __halves2bfloat162(h0, h1);
    __nv_bfloat162 lp = __halves2bfloat162(l0, l1);
    hi = *(unsigned*)&hp;
    lo = *(unsigned*)&lp;
}

__device__ __forceinline__ void mma16(float* c,
    unsigned a0, unsigned a1, unsigned a2, unsigned a3,
    unsigned b0, unsigned b1)
{
    asm volatile(
        "mma.sync.aligned.m16n8k16.row.col.f32.bf16.bf16.f32 "
        "{%0,%1,%2,%3},{%4,%5,%6,%7},{%8,%9},{%0,%1,%2,%3};"
        : "+f"(c[0]), "+f"(c[1]), "+f"(c[2]), "+f"(c[3])
        : "r"(a0), "r"(a1), "r"(a2), "r"(a3), "r"(b0), "r"(b1));
}

// ---------------- tensor-core GEMM: 128x128x32 stage, 3xBF16 split ------------
// A staged in fragment-major quads (one quad = the 4 mma A-words), XOR-swizzled
// by (gid>>1)&3 and by 2*substep: producer STS and consumer LDS.128 both
// conflict-free. B staged k2-major. Double-buffered, one sync per 32-deep K.
// mode 0: C = A@B + bias (+res); mode 1: g_H=gelu(gather@W1+b1);
// mode 2: g_part[slot][tok] = gate*(g_H@W2+b2)
#define LDSW 136
// dynamic smem layout: Aq quads [buf][plane][512] (32768 B), then
// Bs words [buf][plane][16][LDSW] (34816 B)
#define SMEM_AQ   32768
#define SMEM_GEMM (SMEM_AQ + 2 * 2 * 16 * LDSW * 4)

__global__ __launch_bounds__(256, 2) void gemm_bf16_kernel(
    int mode,
    const float* __restrict__ A, const float* __restrict__ Bmat,
    const float* __restrict__ bias, const float* __restrict__ res,
    float* __restrict__ Cout, int M, int N, int K)
{
    extern __shared__ char smdyn[];
    uint4*    Aq = (uint4*)smdyn;                    // [(buf*2+plane)*512 + q]
    unsigned* Bs = (unsigned*)(smdyn + SMEM_AQ);     // [((buf*2+plane)*16+k2)*LDSW + c]

    const int e  = blockIdx.z;
    const int bm = blockIdx.y * 128;
    const int bn = blockIdx.x * 128;
    int cnt = M;
    if (mode != 0) {
        cnt = g_cnt[e];
        if (bm >= cnt) return;
    }

    const float* Bp    = Bmat;
    const float* biasp = bias;
    if (mode == 1)      { Bp = Bmat + (size_t)e * CD * DFF; biasp = bias + e * DFF; }
    else if (mode == 2) { Bp = Bmat + (size_t)e * DFF * CD; biasp = bias + e * CD; }

    const int t = threadIdx.x;
    // A producer: 2 threads per row; thread covers one 16-k substep of the stage
    const int arow   = t >> 1;
    const int ahalf  = t & 1;              // substep index this thread fills
    const int amtile = arow >> 4;
    const int agid   = arow & 7;
    const int ab3    = (arow >> 3) & 1;
    const int aswz   = (agid >> 1) & 3;
    const float* aptr = nullptr;
    {
        const int r = bm + arow;
        if (mode == 0)      aptr = A + (size_t)r * K;
        else if (r < cnt) {
            if (mode == 1)  aptr = A + (size_t)g_tok[e * BT + r] * CD;
            else            aptr = A + ((size_t)e * BT + r) * DFF;   // A = g_H
        }
    }
    // B producer: thread covers 2 adjacent k rows x 8 cols
    const int bk2   = t >> 4;              // 0..15 (local k2 row)
    const int bcolT = (t & 15) * 8;
    const float* bptr = Bp + (size_t)(2 * bk2) * N + bn + bcolT;

    // warp tiling: 2 (M) x 4 (N) warps; warp tile 64x32; mma m16n8k16
    const int w = t >> 5, lane = t & 31;
    const int gid = lane >> 2, tig = lane & 3;
    const int m0 = (w >> 2) * 64;
    const int n0 = (w & 3) * 32;

    float acc[4][4][4];
    #pragma unroll
    for (int i = 0; i < 4; i++)
        #pragma unroll
        for (int j = 0; j < 4; j++)
            #pragma unroll
            for (int q = 0; q < 4; q++) acc[i][j][q] = 0.f;

    float fA[16];
    float fB0[8], fB1[8];

    #define LOAD_A(k0)                                                        \
        do {                                                                  \
            if (aptr) {                                                       \
                const float* ap = aptr + (k0) + ahalf * 16;                   \
                *(float4*)&fA[0]  = *(const float4*)(ap);                     \
                *(float4*)&fA[4]  = *(const float4*)(ap + 4);                 \
                *(float4*)&fA[8]  = *(const float4*)(ap + 8);                 \
                *(float4*)&fA[12] = *(const float4*)(ap + 12);                \
            } else {                                                          \
                _Pragma("unroll")                                             \
                for (int i_ = 0; i_ < 16; i_++) fA[i_] = 0.f;                 \
            }                                                                 \
        } while (0)

    #define LOAD_B(k0)                                                        \
        do {                                                                  \
            *(float4*)&fB0[0] = *(const float4*)(bptr + (size_t)(k0) * N);    \
            *(float4*)&fB0[4] = *(const float4*)(bptr + (size_t)(k0) * N + 4);\
            *(float4*)&fB1[0] = *(const float4*)(bptr + (size_t)((k0) + 1) * N);    \
            *(float4*)&fB1[4] = *(const float4*)(bptr + (size_t)((k0) + 1) * N + 4);\
        } while (0)

    #define STORE_TILE(bf)                                                    \
        do {                                                                  \
            const int qh_ = ahalf * 256 + amtile * 32 + agid * 4;             \
            _Pragma("unroll")                                                 \
            for (int j_ = 0; j_ < 8; j_++) {                                  \
                unsigned h_, l_;                                              \
                split_pack(fA[2 * j_], fA[2 * j_ + 1], h_, l_);               \
                const int q_ = qh_ + (((j_ & 3) ^ aswz ^ (ahalf << 1)) & 3);  \
                const int slot_ = 2 * (j_ >> 2) + ab3;                        \
                ((unsigned*)&Aq[((bf) * 2 + 0) * 512 + q_])[slot_] = h_;      \
                ((unsigned*)&Aq[((bf) * 2 + 1) * 512 + q_])[slot_] = l_;      \
            }                                                                 \
            unsigned bh_[8], bl_[8];                                          \
            _Pragma("unroll")                                                 \
            for (int i_ = 0; i_ < 8; i_++)                                    \
                split_pack(fB0[i_], fB1[i_], bh_[i_], bl_[i_]);               \
            unsigned* bp0_ = &Bs[(((bf) * 2 + 0) * 16 + bk2) * LDSW + bcolT]; \
            unsigned* bp1_ = &Bs[(((bf) * 2 + 1) * 16 + bk2) * LDSW + bcolT]; \
            *(uint4*)(bp0_)     = make_uint4(bh_[0], bh_[1], bh_[2], bh_[3]); \
            *(uint4*)(bp0_ + 4) = make_uint4(bh_[4], bh_[5], bh_[6], bh_[7]); \
            *(uint4*)(bp1_)     = make_uint4(bl_[0], bl_[1], bl_[2], bl_[3]); \
            *(uint4*)(bp1_ + 4) = make_uint4(bl_[4], bl_[5], bl_[6], bl_[7]); \
        } while (0)

    #define COMPUTE(bufv, s)                                                  \
        do {                                                                  \
            unsigned bh[4][2], bl[4][2];                                      \
            const int kr0_ = (s) * 8 + tig;                                   \
            _Pragma("unroll")                                                 \
            for (int nt = 0; nt < 4; nt++) {                                  \
                const int n_ = n0 + nt * 8 + gid;                             \
                bh[nt][0] = Bs[(((bufv) * 2 + 0) * 16 + kr0_) * LDSW + n_];       \
                bh[nt][1] = Bs[(((bufv) * 2 + 0) * 16 + kr0_ + 4) * LDSW + n_];   \
                bl[nt][0] = Bs[(((bufv) * 2 + 1) * 16 + kr0_) * LDSW + n_];       \
                bl[nt][1] = Bs[(((bufv) * 2 + 1) * 16 + kr0_ + 4) * LDSW + n_];   \
            }                                                                 \
            const int qb_ = (s) * 256 + (m0 >> 4) * 32 + gid * 4              \
                          + ((tig ^ (gid >> 1) ^ ((s) << 1)) & 3);            \
            _Pragma("unroll")                                                 \
            for (int mt = 0; mt < 4; mt++) {                                  \
                const uint4 vh = Aq[((bufv) * 2 + 0) * 512 + qb_ + mt * 32];  \
                const uint4 vl = Aq[((bufv) * 2 + 1) * 512 + qb_ + mt * 32];  \
                _Pragma("unroll")                                             \
                for (int nt = 0; nt < 4; nt++) {                              \
                    mma16(acc[mt][nt], vh.x, vh.y, vh.z, vh.w, bh[nt][0], bh[nt][1]); \
                    mma16(acc[mt][nt], vl.x, vl.y, vl.z, vl.w, bh[nt][0], bh[nt][1]); \
                    mma16(acc[mt][nt], vh.x, vh.y, vh.z, vh.w, bl[nt][0], bl[nt][1]); \
                }                                                             \
            }                                                                 \
        } while (0)

    LOAD_A(0);
    LOAD_B(0);
    STORE_TILE(0);
    __syncthreads();

    int buf = 0;
    for (int k0 = 0; k0 < K; k0 += 32) {
        const bool more = (k0 + 32 < K);
        if (more) LOAD_A(k0 + 32);        // A LDG covered by both substeps
        COMPUTE(buf, 0);
        if (more) LOAD_B(k0 + 32);        // B LDG covered by substep 1
        COMPUTE(buf, 1);
        if (more) STORE_TILE(buf ^ 1);    // waits on LDGs; fills other buffer
        __syncthreads();
        buf ^= 1;
    }
    #undef LOAD_A
    #undef LOAD_B
    #undef STORE_TILE
    #undef COMPUTE

    // ---- epilogue ----
    #pragma unroll
    for (int mt = 0; mt < 4; mt++) {
        #pragma unroll
        for (int rr = 0; rr < 2; rr++) {
            const int row = bm + m0 + mt * 16 + gid + rr * 8;
            if (mode != 0 && row >= cnt) continue;

            float* orow;
            float gate = 1.0f;
            if (mode == 0) {
                orow = Cout + (size_t)row * N;
            } else if (mode == 1) {
                orow = g_H + ((size_t)e * BT + row) * DFF;
            } else {
                const int tok  = g_tok [e * BT + row];
                const int slot = g_slot[e * BT + row];
                gate           = g_gate[e * BT + row];
                orow = g_part + (size_t)slot * BT * CD + (size_t)tok * CD;
            }

            #pragma unroll
            for (int nt = 0; nt < 4; nt++) {
                const int nc = bn + n0 + nt * 8 + 2 * tig;
                float v0 = acc[mt][nt][rr * 2 + 0] + biasp[nc];
                float v1 = acc[mt][nt][rr * 2 + 1] + biasp[nc + 1];
                if (mode == 0) {
                    if (res) {
                        const float2 r2 = *(const float2*)(res + (size_t)row * N + nc);
                        v0 += r2.x; v1 += r2.y;
                    }
                } else if (mode == 1) {
                    v0 = 0.5f * v0 * (1.0f + erff(v0 * 0.70710678118654752f));
                    v1 = 0.5f * v1 * (1.0f + erff(v1 * 0.70710678118654752f));
                } else {
                    v0 *= gate; v1 *= gate;
                }
                *(float2*)(orow + nc) = make_float2(v0, v1);
            }
        }
    }
}

// ---------------- flash attention: 64-row Q tile, 32-key tiles ----------------
__global__ __launch_bounds__(256) void attn_kernel(
    const float* __restrict__ qkv, float* __restrict__ y)
{
    __shared__ float Qs[64][64];
    __shared__ float Ks[32][65];
    __shared__ float Vs[32][64];
    __shared__ float Ps[64][33];

    const int qt = blockIdx.x, h = blockIdx.y, b = blockIdx.z;
    const int t = threadIdx.x;
    const int tr = t >> 4, tc = t & 15;
    const int r0  = tr * 4;
    const int c0s = tc * 2;
    const int c0o = tc * 4;

    const float* qbase = qkv + (size_t)(b * TT + qt * 64) * QKVW + h * HDIM;
    const float* kbase = qkv + (size_t)(b * TT) * QKVW + CD + h * HDIM;
    const float* vbase = kbase + CD;

    {
        const int rr = t >> 4;
        const int d4 = (t & 15) * 4;
        #pragma unroll
        for (int i = 0; i < 4; i++) {
            float4 v = *(const float4*)(qbase + (size_t)(rr + 16 * i) * QKVW + d4);
            v.x *= 0.125f; v.y *= 0.125f; v.z *= 0.125f; v.w *= 0.125f;
            *(float4*)&Qs[rr + 16 * i][d4] = v;
        }
    }

    float O[4][4];
    float m_i[4], l_i[4];
    #pragma unroll
    for (int i = 0; i < 4; i++) {
        m_i[i] = -INFINITY; l_i[i] = 0.f;
        #pragma unroll
        for (int j = 0; j < 4; j++) O[i][j] = 0.f;
    }

    const int nkt = 2 * qt + 2;
    for (int kt = 0; kt < nkt; kt++) {
        __syncthreads();
        {
            const int c  = t >> 3;
            const int d4 = (t & 7) * 4;
            #pragma unroll
            for (int i = 0; i < 2; i++) {
                const int d = d4 + 32 * i;
                const float4 kv = *(const float4*)(kbase + (size_t)(kt * 32 + c) * QKVW + d);
                Ks[c][d + 0] = kv.x; Ks[c][d + 1] = kv.y;
                Ks[c][d + 2] = kv.z; Ks[c][d + 3] = kv.w;
                const float4 vv = *(const float4*)(vbase + (size_t)(kt * 32 + c) * QKVW + d);
                *(float4*)&Vs[c][d] = vv;
            }
        }
        __syncthreads();

        float s[4][2];
        #pragma unroll
        for (int i = 0; i < 4; i++) { s[i][0] = 0.f; s[i][1] = 0.f; }
        #pragma unroll 8
        for (int d = 0; d < 64; d++) {
            const float k0v = Ks[c0s][d], k1v = Ks[c0s + 1][d];
            #pragma unroll
            for (int i = 0; i < 4; i++) {
                const float a = Qs[r0 + i][d];
                s[i][0] += a * k0v;
                s[i][1] += a * k1v;
            }
        }
        const int qg0 = qt * 64 + r0;
        const int kg0 = kt * 32 + c0s;
        #pragma unroll
        for (int i = 0; i < 4; i++)
            #pragma unroll
            for (int j = 0; j < 2; j++)
                if (kg0 + j > qg0 + i) s[i][j] = -INFINITY;

        #pragma unroll
        for (int i = 0; i < 4; i++) {
            float mx = fmaxf(s[i][0], s[i][1]);
            #pragma unroll
            for (int m = 8; m >= 1; m >>= 1)
                mx = fmaxf(mx, __shfl_xor_sync(0xffffffffu, mx, m));
            const float mnew = fmaxf(m_i[i], mx);
            const float scale = expf(m_i[i] - mnew);
            const float p0 = expf(s[i][0] - mnew);
            const float p1 = expf(s[i][1] - mnew);
            float rs = p0 + p1;
            #pragma unroll
            for (int m = 8; m >= 1; m >>= 1)
                rs += __shfl_xor_sync(0xffffffffu, rs, m);
            l_i[i] = l_i[i] * scale + rs;
            m_i[i] = mnew;
            #pragma unroll
            for (int j = 0; j < 4; j++) O[i][j] *= scale;
            Ps[r0 + i][c0s]     = p0;
            Ps[r0 + i][c0s + 1] = p1;
        }
        __syncthreads();

        #pragma unroll 4
        for (int k = 0; k < 32; k++) {
            const float4 vv = *(const float4*)&Vs[k][c0o];
            #pragma unroll
            for (int i = 0; i < 4; i++) {
                const float p = Ps[r0 + i][k];
                O[i][0] += p * vv.x;
                O[i][1] += p * vv.y;
                O[i][2] += p * vv.z;
                O[i][3] += p * vv.w;
            }
        }
    }

    float* ybase = y + (size_t)(b * TT + qt * 64) * CD + h * HDIM;
    #pragma unroll
    for (int i = 0; i < 4; i++) {
        const float inv = 1.0f / l_i[i];
        float4 o;
        o.x = O[i][0] * inv; o.y = O[i][1] * inv;
        o.z = O[i][2] * inv; o.w = O[i][3] * inv;
        *(float4*)(ybase + (size_t)(r0 + i) * CD + c0o) = o;
    }
}

// ---------------- router: softmax + top-2 + token gather ----------------------
__global__ __launch_bounds__(128) void router_kernel(
    const float* __restrict__ xn2, const float* __restrict__ Wr)
{
    const int tkn = blockIdx.x;
    const int t = threadIdx.x;
    const int e = t & 15, ch = t >> 4;
    __shared__ float part[8][16];
    __shared__ float logits[16];

    const float* xr = xn2 + (size_t)tkn * CD;
    float s = 0.f;
    for (int k = ch; k < CD; k += 8) s += xr[k] * Wr[k * NE + e];
    part[ch][e] = s;
    __syncthreads();
    if (t < 16) {
        float l = 0.f;
        #pragma unroll
        for (int c = 0; c < 8; c++) l += part[c][t];
        logits[t] = l;
    }
    __syncthreads();
    if (t == 0) {
        float mx = logits[0];
        #pragma unroll
        for (int i = 1; i < NE; i++) mx = fmaxf(mx, logits[i]);
        float p[NE], sum = 0.f;
        #pragma unroll
        for (int i = 0; i < NE; i++) { p[i] = expf(logits[i] - mx); sum += p[i]; }
        const float inv = 1.0f / sum;
        int i0 = 0; float p0 = p[0];
        #pragma unroll
        for (int i = 1; i < NE; i++) if (p[i] > p0) { p0 = p[i]; i0 = i; }
        int i1 = -1; float p1 = -INFINITY;
        #pragma unroll
        for (int i = 0; i < NE; i++) if (i != i0 && p[i] > p1) { p1 = p[i]; i1 = i; }
        p0 *= inv; p1 *= inv;
        int pos = atomicAdd(&g_cnt[i0], 1);
        g_tok [i0 * BT + pos] = tkn;
        g_slot[i0 * BT + pos] = 0;
        g_gate[i0 * BT + pos] = p0;
        pos = atomicAdd(&g_cnt[i1], 1);
        g_tok [i1 * BT + pos] = tkn;
        g_slot[i1 * BT + pos] = 1;
        g_gate[i1 * BT + pos] = p1;
    }
}

__global__ void init_kernel() { if (threadIdx.x < NE) g_cnt[threadIdx.x] = 0; }

// ---------------- final: out = x1 + xn2 + part0 + part1 -----------------------
__global__ __launch_bounds__(256) void final_kernel(float* __restrict__ out)
{
    const int i = blockIdx.x * 256 + threadIdx.x;
    out[i] = g_x1[i] + g_xn2[i] + g_part[i] + g_part[BT * CD + i];
}

// ---------------- launch -------------------------------------------------------
extern "C" void kernel_launch(void* const* d_in, const int* in_sizes, int n_in,
                              void* d_out, int out_size)
{
    const float* x        = (const float*)d_in[0];
    const float* ln1_w    = (const float*)d_in[1];
    const float* ln1_b    = (const float*)d_in[2];
    const float* W_attn   = (const float*)d_in[3];
    const float* b_attn   = (const float*)d_in[4];
    const float* W_proj   = (const float*)d_in[5];
    const float* b_proj   = (const float*)d_in[6];
    const float* ln2_w    = (const float*)d_in[7];
    const float* ln2_b    = (const float*)d_in[8];
    const float* W_router = (const float*)d_in[9];
    const float* W1       = (const float*)d_in[10];
    const float* b1       = (const float*)d_in[11];
    const float* W2       = (const float*)d_in[12];
    const float* b2       = (const float*)d_in[13];
    float* out = (float*)d_out;

    float *p_xn, *p_qkv, *p_y, *p_x1, *p_xn2, *p_H;
    cudaGetSymbolAddress((void**)&p_xn,  g_xn);
    cudaGetSymbolAddress((void**)&p_qkv, g_qkv);
    cudaGetSymbolAddress((void**)&p_y,   g_y);
    cudaGetSymbolAddress((void**)&p_x1,  g_x1);
    cudaGetSymbolAddress((void**)&p_xn2, g_xn2);
    cudaGetSymbolAddress((void**)&p_H,   g_H);

    cudaFuncSetAttribute(gemm_bf16_kernel,
                         cudaFuncAttributeMaxDynamicSharedMemorySize, SMEM_GEMM);

    // attention sublayer
    ln_kernel<<<BT, 256>>>(x, ln1_w, ln1_b, p_xn);
    gemm_bf16_kernel<<<dim3(QKVW / 128, BT / 128, 1), 256, SMEM_GEMM>>>(
        0, p_xn, W_attn, b_attn, nullptr, p_qkv, BT, QKVW, CD);
    attn_kernel<<<dim3(TT / 64, NH, 4), 256>>>(p_qkv, p_y);
    gemm_bf16_kernel<<<dim3(CD / 128, BT / 128, 1), 256, SMEM_GEMM>>>(
        0, p_y, W_proj, b_proj, x, p_x1, BT, CD, CD);

    // MoE sublayer
    ln_kernel<<<BT, 256>>>(p_x1, ln2_w, ln2_b, p_xn2);
    init_kernel<<<1, 32>>>();
    router_kernel<<<BT, 128>>>(p_xn2, W_router);
    gemm_bf16_kernel<<<dim3(DFF / 128, BT / 128, NE), 256, SMEM_GEMM>>>(
        1, p_xn2, W1, b1, nullptr, nullptr, BT, DFF, CD);
    gemm_bf16_kernel<<<dim3(CD / 128, BT / 128, NE), 256, SMEM_GEMM>>>(
        2, p_H, W2, b2, nullptr, nullptr, BT, CD, DFF);

    // out = x1 + xn2 + y_moe
    final_kernel<<<BT * CD / 256, 256>>>(out);
}

// round 17
// speedup vs baseline: 1.3195x; 1.3195x over previous
#include <cuda_runtime.h>
#include <cuda_bf16.h>
#include <math.h>
#include <stdint.h>

#define BT   4096      // B*T
#define CD   768       // C
#define TT   1024      // T
#define NH   12
#define HDIM 64
#define NE   16
#define DFF  3072
#define QKVW 2304      // 3*C

// ---------------- scratch (device globals: allocation-free kernel_launch) ----
__device__ float g_xn  [BT * CD];
__device__ float g_qkv [BT * QKVW];
__device__ float g_y   [BT * CD];
__device__ float g_x1  [BT * CD];
__device__ float g_xn2 [BT * CD];
__device__ float g_part[2 * BT * CD];
__device__ float g_H   [NE * BT * DFF];
__device__ int   g_cnt [NE];
__device__ int   g_tok [NE * BT];
__device__ int   g_slot[NE * BT];
__device__ float g_gate[NE * BT];

// ---------------- LayerNorm ---------------------------------------------------
__global__ __launch_bounds__(256) void ln_kernel(
    const float* __restrict__ x, const float* __restrict__ w,
    const float* __restrict__ b, float* __restrict__ out)
{
    const int row = blockIdx.x;
    const int t = threadIdx.x;
    const float* xr = x + (size_t)row * CD;
    __shared__ float sh[8];

    float a0 = xr[t], a1 = xr[t + 256], a2 = xr[t + 512];
    float s = a0 + a1 + a2;
    #pragma unroll
    for (int m = 16; m >= 1; m >>= 1) s += __shfl_xor_sync(0xffffffffu, s, m);
    if ((t & 31) == 0) sh[t >> 5] = s;
    __syncthreads();
    float mu = 0.f;
    #pragma unroll
    for (int i = 0; i < 8; i++) mu += sh[i];
    mu *= (1.0f / CD);
    __syncthreads();

    float d0 = a0 - mu, d1 = a1 - mu, d2 = a2 - mu;
    float v = d0 * d0 + d1 * d1 + d2 * d2;
    #pragma unroll
    for (int m = 16; m >= 1; m >>= 1) v += __shfl_xor_sync(0xffffffffu, v, m);
    if ((t & 31) == 0) sh[t >> 5] = v;
    __syncthreads();
    float var = 0.f;
    #pragma unroll
    for (int i = 0; i < 8; i++) var += sh[i];
    var *= (1.0f / CD);
    const float rstd = rsqrtf(var + 1e-5f);

    float* orow = out + (size_t)row * CD;
    orow[t      ] = d0 * rstd * w[t      ] + b[t      ];
    orow[t + 256] = d1 * rstd * w[t + 256] + b[t + 256];
    orow[t + 512] = d2 * rstd * w[t + 512] + b[t + 512];
}

// ---------------- bf16 helpers ------------------------------------------------
__device__ __forceinline__ void split_pack(float x0, float x1,
                                           unsigned& hi, unsigned& lo)
{
    __nv_bfloat16 h0 = __float2bfloat16(x0);
    __nv_bfloat16 h1 = __float2bfloat16(x1);
    float r0 = x0 - __bfloat162float(h0);
    float r1 = x1 - __bfloat162float(h1);
    __nv_bfloat16 l0 = __float2bfloat16(r0);
    __nv_bfloat16 l1 = __float2bfloat16(r1);
    __nv_bfloat162 hp = __halves2bfloat162(h0, h1);
    __nv_bfloat162 lp = __halves2bfloat162(l0, l1);
    hi = *(unsigned*)&hp;
    lo = *(unsigned*)&lp;
}

__device__ __forceinline__ void mma16(float* c,
    unsigned a0, unsigned a1, unsigned a2, unsigned a3,
    unsigned b0, unsigned b1)
{
    asm volatile(
        "mma.sync.aligned.m16n8k16.row.col.f32.bf16.bf16.f32 "
        "{%0,%1,%2,%3},{%4,%5,%6,%7},{%8,%9},{%0,%1,%2,%3};"
        : "+f"(c[0]), "+f"(c[1]), "+f"(c[2]), "+f"(c[3])
        : "r"(a0), "r"(a1), "r"(a2), "r"(a3), "r"(b0), "r"(b1));
}

// ---------------- tensor-core GEMM: 128x128x16, 3xBF16 split ------------------
// A staged in fragment-major quads; compute runs three 16-mma passes
// (hi*Bhi, hi*Blo, lo*Bhi) so same-accumulator reuse distance is 16 mmas
// (covers HMMA latency; no acc-RAW stalls).
// mode 0: C = A@B + bias (+res); mode 1: g_H=gelu(gather@W1+b1);
// mode 2: g_part[slot][tok] = gate*(g_H@W2+b2)
#define LDSW 136

__global__ __launch_bounds__(256, 2) void gemm_bf16_kernel(
    int mode,
    const float* __restrict__ A, const float* __restrict__ Bmat,
    const float* __restrict__ bias, const float* __restrict__ res,
    float* __restrict__ Cout, int M, int N, int K)
{
    __shared__ uint4    Aq[2][2][256];                    // [buf][hi/lo][quad]
    __shared__ unsigned Bs_hi[2][8][LDSW], Bs_lo[2][8][LDSW];

    const int e  = blockIdx.z;
    const int bm = blockIdx.y * 128;
    const int bn = blockIdx.x * 128;
    int cnt = M;
    if (mode != 0) {
        cnt = g_cnt[e];
        if (bm >= cnt) return;
    }

    const float* Bp    = Bmat;
    const float* biasp = bias;
    if (mode == 1)      { Bp = Bmat + (size_t)e * CD * DFF; biasp = bias + e * DFF; }
    else if (mode == 2) { Bp = Bmat + (size_t)e * DFF * CD; biasp = bias + e * CD; }

    const int t = threadIdx.x;
    // A loader: 2 threads per row, 8 consecutive k each
    const int arow  = t >> 1;
    const int acol  = (t & 1) * 8;         // k float offset within 16-tile
    const int ahalf = t & 1;               // k2 group: 0 -> k2 0..3, 1 -> k2 4..7
    const int amtile = arow >> 4;
    const int agid   = arow & 7;
    const int ab3    = (arow >> 3) & 1;
    const int aswz   = (agid >> 1) & 3;
    const int awslot = 2 * ahalf + ab3;    // word slot within quad
    const float* aptr = nullptr;
    {
        const int r = bm + arow;
        if (mode == 0)      aptr = A + (size_t)r * K;
        else if (r < cnt) {
            if (mode == 1)  aptr = A + (size_t)g_tok[e * BT + r] * CD;
            else            aptr = A + ((size_t)e * BT + r) * DFF;   // A = g_H
        }
    }
    // B loader: thread covers 2 adjacent k rows x 4 cols (packs k-pairs)
    const int bk2  = t >> 5;               // 0..7
    const int bcol = (t & 31) * 4;
    const float* bptr = Bp + (size_t)(2 * bk2) * N + bn + bcol;

    // warp tiling: 2 (M) x 4 (N) warps; warp tile 64x32; mma m16n8k16
    const int w = t >> 5, lane = t & 31;
    const int gid = lane >> 2, tig = lane & 3;
    const int m0 = (w >> 2) * 64;
    const int n0 = (w & 3) * 32;
    const int qbase = ((m0 >> 4) * 32) + gid * 4 + (tig ^ ((gid >> 1) & 3));

    float acc[4][4][4];
    #pragma unroll
    for (int i = 0; i < 4; i++)
        #pragma unroll
        for (int j = 0; j < 4; j++)
            #pragma unroll
            for (int q = 0; q < 4; q++) acc[i][j][q] = 0.f;

    float av[8];
    float bu0[4], bu1[4];

    #define LOAD_TILE(k0)                                                    \
        do {                                                                 \
            if (aptr) {                                                      \
                const float4 v0 = *(const float4*)(aptr + (k0) + acol);      \
                const float4 v1 = *(const float4*)(aptr + (k0) + acol + 4);  \
                av[0] = v0.x; av[1] = v0.y; av[2] = v0.z; av[3] = v0.w;      \
                av[4] = v1.x; av[5] = v1.y; av[6] = v1.z; av[7] = v1.w;      \
            } else {                                                         \
                _Pragma("unroll")                                            \
                for (int i_ = 0; i_ < 8; i_++) av[i_] = 0.f;                 \
            }                                                                \
            const float4 u0 = *(const float4*)(bptr + (size_t)(k0) * N);     \
            const float4 u1 = *(const float4*)(bptr + (size_t)((k0) + 1) * N); \
            bu0[0] = u0.x; bu0[1] = u0.y; bu0[2] = u0.z; bu0[3] = u0.w;      \
            bu1[0] = u1.x; bu1[1] = u1.y; bu1[2] = u1.z; bu1[3] = u1.w;      \
        } while (0)

    #define STORE_TILE(bf)                                                   \
        do {                                                                 \
            _Pragma("unroll")                                                \
            for (int i_ = 0; i_ < 4; i_++) {                                 \
                unsigned h_, l_;                                             \
                split_pack(av[2 * i_], av[2 * i_ + 1], h_, l_);              \
                const int q_ = amtile * 32 + agid * 4 + (i_ ^ aswz);         \
                ((unsigned*)&Aq[bf][0][q_])[awslot] = h_;                    \
                ((unsigned*)&Aq[bf][1][q_])[awslot] = l_;                    \
            }                                                                \
            unsigned bh_[4], bl_[4];                                         \
            _Pragma("unroll")                                                \
            for (int i_ = 0; i_ < 4; i_++)                                   \
                split_pack(bu0[i_], bu1[i_], bh_[i_], bl_[i_]);              \
            *(uint4*)&Bs_hi[bf][bk2][bcol] = make_uint4(bh_[0], bh_[1], bh_[2], bh_[3]); \
            *(uint4*)&Bs_lo[bf][bk2][bcol] = make_uint4(bl_[0], bl_[1], bl_[2], bl_[3]); \
        } while (0)

    LOAD_TILE(0);
    STORE_TILE(0);
    __syncthreads();

    int buf = 0;
    for (int k0 = 0; k0 < K; k0 += 16) {
        const bool more = (k0 + 16 < K);
        if (more) LOAD_TILE(k0 + 16);      // LDG issued; latency hidden by compute

        // ---- compute from current buffer: three 16-mma passes ----
        {
            unsigned bh[4][2], bl[4][2];
            #pragma unroll
            for (int nt = 0; nt < 4; nt++) {
                const int n = n0 + nt * 8 + gid;
                bh[nt][0] = Bs_hi[buf][tig][n];     bh[nt][1] = Bs_hi[buf][tig + 4][n];
                bl[nt][0] = Bs_lo[buf][tig][n];     bl[nt][1] = Bs_lo[buf][tig + 4][n];
            }
            uint4 vh[4];
            #pragma unroll
            for (int mt = 0; mt < 4; mt++) vh[mt] = Aq[buf][0][qbase + mt * 32];

            // pass 1: hi * Bhi  (16 mmas, distinct accumulators)
            #pragma unroll
            for (int mt = 0; mt < 4; mt++)
                #pragma unroll
                for (int nt = 0; nt < 4; nt++)
                    mma16(acc[mt][nt], vh[mt].x, vh[mt].y, vh[mt].z, vh[mt].w,
                          bh[nt][0], bh[nt][1]);
            // pass 2: hi * Blo
            #pragma unroll
            for (int mt = 0; mt < 4; mt++)
                #pragma unroll
                for (int nt = 0; nt < 4; nt++)
                    mma16(acc[mt][nt], vh[mt].x, vh[mt].y, vh[mt].z, vh[mt].w,
                          bl[nt][0], bl[nt][1]);
            // pass 3: lo * Bhi
            uint4 vl[4];
            #pragma unroll
            for (int mt = 0; mt < 4; mt++) vl[mt] = Aq[buf][1][qbase + mt * 32];
            #pragma unroll
            for (int mt = 0; mt < 4; mt++)
                #pragma unroll
                for (int nt = 0; nt < 4; nt++)
                    mma16(acc[mt][nt], vl[mt].x, vl[mt].y, vl[mt].z, vl[mt].w,
                          bh[nt][0], bh[nt][1]);
        }

        if (more) STORE_TILE(buf ^ 1);     // waits on LDG; fills the other buffer
        __syncthreads();
        buf ^= 1;
    }
    #undef LOAD_TILE
    #undef STORE_TILE

    // ---- epilogue ----
    #pragma unroll
    for (int mt = 0; mt < 4; mt++) {
        #pragma unroll
        for (int rr = 0; rr < 2; rr++) {
            const int row = bm + m0 + mt * 16 + gid + rr * 8;
            if (mode != 0 && row >= cnt) continue;

            float* orow;
            float gate = 1.0f;
            if (mode == 0) {
                orow = Cout + (size_t)row * N;
            } else if (mode == 1) {
                orow = g_H + ((size_t)e * BT + row) * DFF;
            } else {
                const int tok  = g_tok [e * BT + row];
                const int slot = g_slot[e * BT + row];
                gate           = g_gate[e * BT + row];
                orow = g_part + (size_t)slot * BT * CD + (size_t)tok * CD;
            }

            #pragma unroll
            for (int nt = 0; nt < 4; nt++) {
                const int nc = bn + n0 + nt * 8 + 2 * tig;
                float v0 = acc[mt][nt][rr * 2 + 0] + biasp[nc];
                float v1 = acc[mt][nt][rr * 2 + 1] + biasp[nc + 1];
                if (mode == 0) {
                    if (res) {
                        const float2 r2 = *(const float2*)(res + (size_t)row * N + nc);
                        v0 += r2.x; v1 += r2.y;
                    }
                } else if (mode == 1) {
                    v0 = 0.5f * v0 * (1.0f + erff(v0 * 0.70710678118654752f));
                    v1 = 0.5f * v1 * (1.0f + erff(v1 * 0.70710678118654752f));
                } else {
                    v0 *= gate; v1 *= gate;
                }
                *(float2*)(orow + nc) = make_float2(v0, v1);
            }
        }
    }
}

// ---------------- flash attention: 64-row Q tile, 32-key tiles ----------------
__global__ __launch_bounds__(256) void attn_kernel(
    const float* __restrict__ qkv, float* __restrict__ y)
{
    __shared__ float Qs[64][64];
    __shared__ float Ks[32][65];
    __shared__ float Vs[32][64];
    __shared__ float Ps[64][33];

    const int qt = blockIdx.x, h = blockIdx.y, b = blockIdx.z;
    const int t = threadIdx.x;
    const int tr = t >> 4, tc = t & 15;
    const int r0  = tr * 4;
    const int c0s = tc * 2;
    const int c0o = tc * 4;

    const float* qbase = qkv + (size_t)(b * TT + qt * 64) * QKVW + h * HDIM;
    const float* kbase = qkv + (size_t)(b * TT) * QKVW + CD + h * HDIM;
    const float* vbase = kbase + CD;

    {
        const int rr = t >> 4;
        const int d4 = (t & 15) * 4;
        #pragma unroll
        for (int i = 0; i < 4; i++) {
            float4 v = *(const float4*)(qbase + (size_t)(rr + 16 * i) * QKVW + d4);
            v.x *= 0.125f; v.y *= 0.125f; v.z *= 0.125f; v.w *= 0.125f;
            *(float4*)&Qs[rr + 16 * i][d4] = v;
        }
    }

    float O[4][4];
    float m_i[4], l_i[4];
    #pragma unroll
    for (int i = 0; i < 4; i++) {
        m_i[i] = -INFINITY; l_i[i] = 0.f;
        #pragma unroll
        for (int j = 0; j < 4; j++) O[i][j] = 0.f;
    }

    const int nkt = 2 * qt + 2;
    for (int kt = 0; kt < nkt; kt++) {
        __syncthreads();
        {
            const int c  = t >> 3;
            const int d4 = (t & 7) * 4;
            #pragma unroll
            for (int i = 0; i < 2; i++) {
                const int d = d4 + 32 * i;
                const float4 kv = *(const float4*)(kbase + (size_t)(kt * 32 + c) * QKVW + d);
                Ks[c][d + 0] = kv.x; Ks[c][d + 1] = kv.y;
                Ks[c][d + 2] = kv.z; Ks[c][d + 3] = kv.w;
                const float4 vv = *(const float4*)(vbase + (size_t)(kt * 32 + c) * QKVW + d);
                *(float4*)&Vs[c][d] = vv;
            }
        }
        __syncthreads();

        float s[4][2];
        #pragma unroll
        for (int i = 0; i < 4; i++) { s[i][0] = 0.f; s[i][1] = 0.f; }
        #pragma unroll 8
        for (int d = 0; d < 64; d++) {
            const float k0v = Ks[c0s][d], k1v = Ks[c0s + 1][d];
            #pragma unroll
            for (int i = 0; i < 4; i++) {
                const float a = Qs[r0 + i][d];
                s[i][0] += a * k0v;
                s[i][1] += a * k1v;
            }
        }
        const int qg0 = qt * 64 + r0;
        const int kg0 = kt * 32 + c0s;
        #pragma unroll
        for (int i = 0; i < 4; i++)
            #pragma unroll
            for (int j = 0; j < 2; j++)
                if (kg0 + j > qg0 + i) s[i][j] = -INFINITY;

        #pragma unroll
        for (int i = 0; i < 4; i++) {
            float mx = fmaxf(s[i][0], s[i][1]);
            #pragma unroll
            for (int m = 8; m >= 1; m >>= 1)
                mx = fmaxf(mx, __shfl_xor_sync(0xffffffffu, mx, m));
            const float mnew = fmaxf(m_i[i], mx);
            const float scale = expf(m_i[i] - mnew);
            const float p0 = expf(s[i][0] - mnew);
            const float p1 = expf(s[i][1] - mnew);
            float rs = p0 + p1;
            #pragma unroll
            for (int m = 8; m >= 1; m >>= 1)
                rs += __shfl_xor_sync(0xffffffffu, rs, m);
            l_i[i] = l_i[i] * scale + rs;
            m_i[i] = mnew;
            #pragma unroll
            for (int j = 0; j < 4; j++) O[i][j] *= scale;
            Ps[r0 + i][c0s]     = p0;
            Ps[r0 + i][c0s + 1] = p1;
        }
        __syncthreads();

        #pragma unroll 4
        for (int k = 0; k < 32; k++) {
            const float4 vv = *(const float4*)&Vs[k][c0o];
            #pragma unroll
            for (int i = 0; i < 4; i++) {
                const float p = Ps[r0 + i][k];
                O[i][0] += p * vv.x;
                O[i][1] += p * vv.y;
                O[i][2] += p * vv.z;
                O[i][3] += p * vv.w;
            }
        }
    }

    float* ybase = y + (size_t)(b * TT + qt * 64) * CD + h * HDIM;
    #pragma unroll
    for (int i = 0; i < 4; i++) {
        const float inv = 1.0f / l_i[i];
        float4 o;
        o.x = O[i][0] * inv; o.y = O[i][1] * inv;
        o.z = O[i][2] * inv; o.w = O[i][3] * inv;
        *(float4*)(ybase + (size_t)(r0 + i) * CD + c0o) = o;
    }
}

// ---------------- router: softmax + top-2 + token gather ----------------------
__global__ __launch_bounds__(128) void router_kernel(
    const float* __restrict__ xn2, const float* __restrict__ Wr)
{
    const int tkn = blockIdx.x;
    const int t = threadIdx.x;
    const int e = t & 15, ch = t >> 4;
    __shared__ float part[8][16];
    __shared__ float logits[16];

    const float* xr = xn2 + (size_t)tkn * CD;
    float s = 0.f;
    for (int k = ch; k < CD; k += 8) s += xr[k] * Wr[k * NE + e];
    part[ch][e] = s;
    __syncthreads();
    if (t < 16) {
        float l = 0.f;
        #pragma unroll
        for (int c = 0; c < 8; c++) l += part[c][t];
        logits[t] = l;
    }
    __syncthreads();
    if (t == 0) {
        float mx = logits[0];
        #pragma unroll
        for (int i = 1; i < NE; i++) mx = fmaxf(mx, logits[i]);
        float p[NE], sum = 0.f;
        #pragma unroll
        for (int i = 0; i < NE; i++) { p[i] = expf(logits[i] - mx); sum += p[i]; }
        const float inv = 1.0f / sum;
        int i0 = 0; float p0 = p[0];
        #pragma unroll
        for (int i = 1; i < NE; i++) if (p[i] > p0) { p0 = p[i]; i0 = i; }
        int i1 = -1; float p1 = -INFINITY;
        #pragma unroll
        for (int i = 0; i < NE; i++) if (i != i0 && p[i] > p1) { p1 = p[i]; i1 = i; }
        p0 *= inv; p1 *= inv;
        int pos = atomicAdd(&g_cnt[i0], 1);
        g_tok [i0 * BT + pos] = tkn;
        g_slot[i0 * BT + pos] = 0;
        g_gate[i0 * BT + pos] = p0;
        pos = atomicAdd(&g_cnt[i1], 1);
        g_tok [i1 * BT + pos] = tkn;
        g_slot[i1 * BT + pos] = 1;
        g_gate[i1 * BT + pos] = p1;
    }
}

__global__ void init_kernel() { if (threadIdx.x < NE) g_cnt[threadIdx.x] = 0; }

// ---------------- final: out = x1 + xn2 + part0 + part1 -----------------------
__global__ __launch_bounds__(256) void final_kernel(float* __restrict__ out)
{
    const int i = blockIdx.x * 256 + threadIdx.x;
    out[i] = g_x1[i] + g_xn2[i] + g_part[i] + g_part[BT * CD + i];
}

// ---------------- launch -------------------------------------------------------
extern "C" void kernel_launch(void* const* d_in, const int* in_sizes, int n_in,
                              void* d_out, int out_size)
{
    const float* x        = (const float*)d_in[0];
    const float* ln1_w    = (const float*)d_in[1];
    const float* ln1_b    = (const float*)d_in[2];
    const float* W_attn   = (const float*)d_in[3];
    const float* b_attn   = (const float*)d_in[4];
    const float* W_proj   = (const float*)d_in[5];
    const float* b_proj   = (const float*)d_in[6];
    const float* ln2_w    = (const float*)d_in[7];
    const float* ln2_b    = (const float*)d_in[8];
    const float* W_router = (const float*)d_in[9];
    const float* W1       = (const float*)d_in[10];
    const float* b1       = (const float*)d_in[11];
    const float* W2       = (const float*)d_in[12];
    const float* b2       = (const float*)d_in[13];
    float* out = (float*)d_out;

    float *p_xn, *p_qkv, *p_y, *p_x1, *p_xn2, *p_H;
    cudaGetSymbolAddress((void**)&p_xn,  g_xn);
    cudaGetSymbolAddress((void**)&p_qkv, g_qkv);
    cudaGetSymbolAddress((void**)&p_y,   g_y);
    cudaGetSymbolAddress((void**)&p_x1,  g_x1);
    cudaGetSymbolAddress((void**)&p_xn2, g_xn2);
    cudaGetSymbolAddress((void**)&p_H,   g_H);

    // attention sublayer
    ln_kernel<<<BT, 256>>>(x, ln1_w, ln1_b, p_xn);
    gemm_bf16_kernel<<<dim3(QKVW / 128, BT / 128, 1), 256>>>(
        0, p_xn, W_attn, b_attn, nullptr, p_qkv, BT, QKVW, CD);
    attn_kernel<<<dim3(TT / 64, NH, 4), 256>>>(p_qkv, p_y);
    gemm_bf16_kernel<<<dim3(CD / 128, BT / 128, 1), 256>>>(
        0, p_y, W_proj, b_proj, x, p_x1, BT, CD, CD);

    // MoE sublayer
    ln_kernel<<<BT, 256>>>(p_x1, ln2_w, ln2_b, p_xn2);
    init_kernel<<<1, 32>>>();
    router_kernel<<<BT, 128>>>(p_xn2, W_router);
    gemm_bf16_kernel<<<dim3(DFF / 128, BT / 128, NE), 256>>>(
        1, p_xn2, W1, b1, nullptr, nullptr, BT, DFF, CD);
    gemm_bf16_kernel<<<dim3(CD / 128, BT / 128, NE), 256>>>(
        2, p_H, W2, b2, nullptr, nullptr, BT, CD, DFF);

    // out = x1 + xn2 + y_moe
    final_kernel<<<BT * CD / 256, 256>>>(out);
}